// round 15
// baseline (speedup 1.0000x reference)
#include <cuda_runtime.h>
#include <math.h>

#define KDIM 64
#define DEG 32
#define N0_MAX 65536

// hop-0 aggregate scratch: 65536 x 64 f32 = 16 MB (static __device__, no alloc)
__device__ float g_agg0[N0_MAX * KDIM];

// reduce across a 16-lane half-warp (xor 8,4,2,1)
__device__ __forceinline__ float half_sum(float v) {
#pragma unroll
    for (int o = 8; o > 0; o >>= 1) v += __shfl_xor_sync(0xffffffffu, v, o);
    return v;
}

// renorm scale: min(1, 1/max(sqrt(ss), 1e-12)) == ss > 1 ? rsqrt(ss) : 1
__device__ __forceinline__ float renorm_scale(float ss) {
    return (ss > 1.0f) ? rsqrtf(ss) : 1.0f;
}

// ============================ hop 0 ============================
// Champion gather layout (half-warp covers 16 neighbors, lane sl owns dims
// [4sl,4sl+3], e[16] register prefetch = MLP 16), now GRID-STRIDE: each warp
// processes 8 nodes, prefetching the NEXT node's index row + target id while
// the current node's gathers/reduction run. Kills the per-node ~600cyc serial
// index prefix (paid once instead of 8x) and cuts block waves 22 -> ~3.
__global__ void __launch_bounds__(128) hop0_kernel(
    const float* __restrict__ entity_emb,
    const int* __restrict__ node_ids0,
    const int* __restrict__ nbr0,
    int n0)
{
    const int w      = threadIdx.x >> 5;
    const int lane   = threadIdx.x & 31;
    const int sub    = lane >> 4;
    const int sl     = lane & 15;
    const int nwarps = gridDim.x << 2;          // total warps in grid

    int node = (blockIdx.x << 2) + w;
    if (node >= n0) return;

    // prologue: indices for the first node
    int cur_idx = __ldg(nbr0 + (size_t)node * DEG + lane);
    int cur_tid = __ldg(node_ids0 + node);

    while (true) {
        // prefetch next node's indices (overlaps with this node's gathers)
        const int nxt = node + nwarps;
        int nxt_idx = 0, nxt_tid = 0;
        if (nxt < n0) {
            nxt_idx = __ldg(nbr0 + (size_t)nxt * DEG + lane);
            nxt_tid = __ldg(node_ids0 + nxt);
        }

        // ---- batched gathers: 16 rows into registers ----
        float4 e[16];
#pragma unroll
        for (int i = 0; i < 16; i++) {
            const int id = __shfl_sync(0xffffffffu, cur_idx, i + (sub << 4));
            e[i] = __ldg((const float4*)(entity_emb + (size_t)id * KDIM) + sl);
        }
        float4 t = __ldg((const float4*)(entity_emb + (size_t)cur_tid * KDIM) + sl);

        // ---- FM accumulate with per-row renorm ----
        float4 s = make_float4(0.f, 0.f, 0.f, 0.f);
        float4 q = make_float4(0.f, 0.f, 0.f, 0.f);
#pragma unroll
        for (int i = 0; i < 16; i++) {
            const float ss = half_sum(e[i].x * e[i].x + e[i].y * e[i].y +
                                      e[i].z * e[i].z + e[i].w * e[i].w);
            const float sc = renorm_scale(ss);
            const float ex = e[i].x * sc, ey = e[i].y * sc;
            const float ez = e[i].z * sc, ew = e[i].w * sc;
            s.x += ex; s.y += ey; s.z += ez; s.w += ew;
            q.x += ex * ex; q.y += ey * ey; q.z += ez * ez; q.w += ew * ew;
        }

        // combine the two half-warps (same dims at lane ^ 16)
        s.x += __shfl_xor_sync(0xffffffffu, s.x, 16);
        s.y += __shfl_xor_sync(0xffffffffu, s.y, 16);
        s.z += __shfl_xor_sync(0xffffffffu, s.z, 16);
        s.w += __shfl_xor_sync(0xffffffffu, s.w, 16);
        q.x += __shfl_xor_sync(0xffffffffu, q.x, 16);
        q.y += __shfl_xor_sync(0xffffffffu, q.y, 16);
        q.z += __shfl_xor_sync(0xffffffffu, q.z, 16);
        q.w += __shfl_xor_sync(0xffffffffu, q.w, 16);

        const float tsc = renorm_scale(half_sum(t.x * t.x + t.y * t.y +
                                                t.z * t.z + t.w * t.w));

        if (sub == 0) {
            float4 o;
            o.x = s.x * s.x - q.x + t.x * tsc;
            o.y = s.y * s.y - q.y + t.y * tsc;
            o.z = s.z * s.z - q.z + t.z * tsc;
            o.w = s.w * s.w - q.w + t.w * tsc;
            *((float4*)(g_agg0 + (size_t)node * KDIM) + sl) = o;
        }

        if (nxt >= n0) break;
        node = nxt;
        cur_idx = nxt_idx;
        cur_tid = nxt_tid;
    }
}

// ============================ hop 1 ============================
// R14 champion verbatim (7.55us): one block (4 warps) per row; warps 1 & 2
// prefetch item/user rows into smem at the top; warp 0 epilogue reads smem.
__global__ void __launch_bounds__(128) hop1_kernel(
    const float* __restrict__ entity_emb,
    const float* __restrict__ user_emb,
    const int* __restrict__ u,
    const int* __restrict__ item_ids,
    const int* __restrict__ nbr1_idx,
    float* __restrict__ out,
    int B)
{
    __shared__ float4 sm_s[4][16];
    __shared__ float4 sm_q[4][16];
    __shared__ float4 sm_t[16];
    __shared__ float4 sm_u[16];

    const int b    = blockIdx.x;
    const int w    = threadIdx.x >> 5;
    const int lane = threadIdx.x & 31;
    const int sub  = lane >> 4;
    const int sl   = lane & 15;
    if (b >= B) return;

    // top-of-kernel prefetch: warp 1 loads item row, warp 2 loads user row
    if (w == 1 && sub == 0) {
        const int it = __ldg(item_ids + b);
        sm_t[sl] = __ldg((const float4*)(entity_emb + (size_t)it * KDIM) + sl);
    }
    if (w == 2 && sub == 0) {
        const int uid = __ldg(u + b);
        sm_u[sl] = __ldg((const float4*)(user_emb + (size_t)uid * KDIM) + sl);
    }

    // lanes 0-7 hold this warp's 8 neighbor indices
    const int myidx = (lane < 8)
        ? __ldg(nbr1_idx + (size_t)b * DEG + w * 8 + lane) : 0;

    float4 e[4];
#pragma unroll
    for (int i = 0; i < 4; i++) {
        const int id = __shfl_sync(0xffffffffu, myidx, (sub << 2) + i);
        e[i] = __ldg((const float4*)(g_agg0 + (size_t)id * KDIM) + sl);
    }

    float4 s = make_float4(0.f, 0.f, 0.f, 0.f);
    float4 q = make_float4(0.f, 0.f, 0.f, 0.f);
#pragma unroll
    for (int i = 0; i < 4; i++) {
        s.x += e[i].x; s.y += e[i].y; s.z += e[i].z; s.w += e[i].w;
        q.x += e[i].x * e[i].x; q.y += e[i].y * e[i].y;
        q.z += e[i].z * e[i].z; q.w += e[i].w * e[i].w;
    }

    s.x += __shfl_xor_sync(0xffffffffu, s.x, 16);
    s.y += __shfl_xor_sync(0xffffffffu, s.y, 16);
    s.z += __shfl_xor_sync(0xffffffffu, s.z, 16);
    s.w += __shfl_xor_sync(0xffffffffu, s.w, 16);
    q.x += __shfl_xor_sync(0xffffffffu, q.x, 16);
    q.y += __shfl_xor_sync(0xffffffffu, q.y, 16);
    q.z += __shfl_xor_sync(0xffffffffu, q.z, 16);
    q.w += __shfl_xor_sync(0xffffffffu, q.w, 16);

    if (sub == 0) { sm_s[w][sl] = s; sm_q[w][sl] = q; }
    __syncthreads();

    if (w == 0) {
        float4 S = sm_s[0][sl], Q = sm_q[0][sl];
#pragma unroll
        for (int j = 1; j < 4; j++) {
            const float4 a = sm_s[j][sl], c = sm_q[j][sl];
            S.x += a.x; S.y += a.y; S.z += a.z; S.w += a.w;
            Q.x += c.x; Q.y += c.y; Q.z += c.z; Q.w += c.w;
        }

        const float4 t   = sm_t[sl];
        const float4 usr = sm_u[sl];

        const float tsc = renorm_scale(half_sum(t.x * t.x + t.y * t.y +
                                                t.z * t.z + t.w * t.w));
        float4 items;
        items.x = S.x * S.x - Q.x + t.x * tsc;
        items.y = S.y * S.y - Q.y + t.y * tsc;
        items.z = S.z * S.z - Q.z + t.z * tsc;
        items.w = S.w * S.w - Q.w + t.w * tsc;

        const float usc = renorm_scale(half_sum(usr.x * usr.x + usr.y * usr.y +
                                                usr.z * usr.z + usr.w * usr.w));
        const float dot = half_sum((usr.x * items.x + usr.y * items.y +
                                    usr.z * items.z + usr.w * items.w) * usc);
        if (lane == 0) out[b] = 1.0f / (1.0f + expf(-dot));
    }
}

extern "C" void kernel_launch(void* const* d_in, const int* in_sizes, int n_in,
                              void* d_out, int out_size)
{
    const float* entity_emb = (const float*)d_in[0];
    const float* user_emb   = (const float*)d_in[1];
    // d_in[2..5] = Wa, ba, Wh, bh : dead code (softmax over singleton axis == 1)
    const int* u         = (const int*)d_in[6];
    const int* item_ids  = (const int*)d_in[7];
    const int* nbr1_idx  = (const int*)d_in[8];
    const int* node_ids0 = (const int*)d_in[9];
    const int* nbr0      = (const int*)d_in[10];

    const int B  = in_sizes[6];   // 2048
    const int n0 = in_sizes[9];   // 65536

    // hop 0: grid-stride, 2048 blocks x 4 warps -> 8 nodes per warp
    hop0_kernel<<<2048, 128>>>(entity_emb, node_ids0, nbr0, n0);
    // hop 1: one block (4 warps) per batch row
    hop1_kernel<<<B, 128>>>(entity_emb, user_emb, u, item_ids, nbr1_idx,
                            (float*)d_out, B);
}

// round 16
// speedup vs baseline: 1.2437x; 1.2437x over previous
#include <cuda_runtime.h>
#include <math.h>

#define KDIM 64
#define DEG 32
#define N0_MAX 65536

// hop-0 aggregate scratch: 65536 x 64 f32 = 16 MB (static __device__, no alloc)
__device__ float g_agg0[N0_MAX * KDIM];

// reduce across a 16-lane half-warp (xor 8,4,2,1)
__device__ __forceinline__ float half_sum(float v) {
#pragma unroll
    for (int o = 8; o > 0; o >>= 1) v += __shfl_xor_sync(0xffffffffu, v, o);
    return v;
}

// renorm scale: min(1, 1/max(sqrt(ss), 1e-12)) == ss > 1 ? rsqrt(ss) : 1
__device__ __forceinline__ float renorm_scale(float ss) {
    return (ss > 1.0f) ? rsqrtf(ss) : 1.0f;
}

// ============================ hop 0 ============================
// Champion (66.2us measured; LTS/DRAM roofline for random 256B gathers).
// One warp per node; half-warp sub covers neighbors {16*sub+i}; lane sl owns
// dims [4sl,4sl+3]; all 16 rows prefetched into registers (MLP 16). No loop
// state may be added here — it breaks ptxas's load batching (R5/R15).
__global__ void __launch_bounds__(128) hop0_kernel(
    const float* __restrict__ entity_emb,
    const int* __restrict__ node_ids0,
    const int* __restrict__ nbr0,
    int n0)
{
    const int node = blockIdx.x * (blockDim.x >> 5) + (threadIdx.x >> 5);
    const int lane = threadIdx.x & 31;
    const int sub  = lane >> 4;
    const int sl   = lane & 15;
    if (node >= n0) return;

    const int myidx = __ldg(nbr0 + (size_t)node * DEG + lane);
    const int tid   = __ldg(node_ids0 + node);

    float4 e[16];
#pragma unroll
    for (int i = 0; i < 16; i++) {
        const int id = __shfl_sync(0xffffffffu, myidx, i + (sub << 4));
        e[i] = __ldg((const float4*)(entity_emb + (size_t)id * KDIM) + sl);
    }
    float4 t = __ldg((const float4*)(entity_emb + (size_t)tid * KDIM) + sl);

    float4 s = make_float4(0.f, 0.f, 0.f, 0.f);
    float4 q = make_float4(0.f, 0.f, 0.f, 0.f);
#pragma unroll
    for (int i = 0; i < 16; i++) {
        const float ss = half_sum(e[i].x * e[i].x + e[i].y * e[i].y +
                                  e[i].z * e[i].z + e[i].w * e[i].w);
        const float sc = renorm_scale(ss);
        const float ex = e[i].x * sc, ey = e[i].y * sc;
        const float ez = e[i].z * sc, ew = e[i].w * sc;
        s.x += ex; s.y += ey; s.z += ez; s.w += ew;
        q.x += ex * ex; q.y += ey * ey; q.z += ez * ez; q.w += ew * ew;
    }

    s.x += __shfl_xor_sync(0xffffffffu, s.x, 16);
    s.y += __shfl_xor_sync(0xffffffffu, s.y, 16);
    s.z += __shfl_xor_sync(0xffffffffu, s.z, 16);
    s.w += __shfl_xor_sync(0xffffffffu, s.w, 16);
    q.x += __shfl_xor_sync(0xffffffffu, q.x, 16);
    q.y += __shfl_xor_sync(0xffffffffu, q.y, 16);
    q.z += __shfl_xor_sync(0xffffffffu, q.z, 16);
    q.w += __shfl_xor_sync(0xffffffffu, q.w, 16);

    const float tsc = renorm_scale(half_sum(t.x * t.x + t.y * t.y +
                                            t.z * t.z + t.w * t.w));

    if (sub == 0) {
        float4 o;
        o.x = s.x * s.x - q.x + t.x * tsc;
        o.y = s.y * s.y - q.y + t.y * tsc;
        o.z = s.z * s.z - q.z + t.z * tsc;
        o.w = s.w * s.w - q.w + t.w * tsc;
        *((float4*)(g_agg0 + (size_t)node * KDIM) + sl) = o;
    }
}

// ============================ hop 1 ============================
// Champion (7.55us): one block (4 warps) per row; warps 1 & 2 prefetch
// item/user rows into smem at the top (overlapped with agg0 gathers); warp 0
// epilogue reads smem only; agg0 gathers via the read-only nc path.
__global__ void __launch_bounds__(128) hop1_kernel(
    const float* __restrict__ entity_emb,
    const float* __restrict__ user_emb,
    const int* __restrict__ u,
    const int* __restrict__ item_ids,
    const int* __restrict__ nbr1_idx,
    float* __restrict__ out,
    int B)
{
    __shared__ float4 sm_s[4][16];
    __shared__ float4 sm_q[4][16];
    __shared__ float4 sm_t[16];
    __shared__ float4 sm_u[16];

    const int b    = blockIdx.x;
    const int w    = threadIdx.x >> 5;
    const int lane = threadIdx.x & 31;
    const int sub  = lane >> 4;
    const int sl   = lane & 15;
    if (b >= B) return;

    // top-of-kernel prefetch: warp 1 loads item row, warp 2 loads user row
    if (w == 1 && sub == 0) {
        const int it = __ldg(item_ids + b);
        sm_t[sl] = __ldg((const float4*)(entity_emb + (size_t)it * KDIM) + sl);
    }
    if (w == 2 && sub == 0) {
        const int uid = __ldg(u + b);
        sm_u[sl] = __ldg((const float4*)(user_emb + (size_t)uid * KDIM) + sl);
    }

    // lanes 0-7 hold this warp's 8 neighbor indices
    const int myidx = (lane < 8)
        ? __ldg(nbr1_idx + (size_t)b * DEG + w * 8 + lane) : 0;

    float4 e[4];
#pragma unroll
    for (int i = 0; i < 4; i++) {
        const int id = __shfl_sync(0xffffffffu, myidx, (sub << 2) + i);
        e[i] = __ldg((const float4*)(g_agg0 + (size_t)id * KDIM) + sl);
    }

    float4 s = make_float4(0.f, 0.f, 0.f, 0.f);
    float4 q = make_float4(0.f, 0.f, 0.f, 0.f);
#pragma unroll
    for (int i = 0; i < 4; i++) {
        s.x += e[i].x; s.y += e[i].y; s.z += e[i].z; s.w += e[i].w;
        q.x += e[i].x * e[i].x; q.y += e[i].y * e[i].y;
        q.z += e[i].z * e[i].z; q.w += e[i].w * e[i].w;
    }

    s.x += __shfl_xor_sync(0xffffffffu, s.x, 16);
    s.y += __shfl_xor_sync(0xffffffffu, s.y, 16);
    s.z += __shfl_xor_sync(0xffffffffu, s.z, 16);
    s.w += __shfl_xor_sync(0xffffffffu, s.w, 16);
    q.x += __shfl_xor_sync(0xffffffffu, q.x, 16);
    q.y += __shfl_xor_sync(0xffffffffu, q.y, 16);
    q.z += __shfl_xor_sync(0xffffffffu, q.z, 16);
    q.w += __shfl_xor_sync(0xffffffffu, q.w, 16);

    if (sub == 0) { sm_s[w][sl] = s; sm_q[w][sl] = q; }
    __syncthreads();

    if (w == 0) {
        float4 S = sm_s[0][sl], Q = sm_q[0][sl];
#pragma unroll
        for (int j = 1; j < 4; j++) {
            const float4 a = sm_s[j][sl], c = sm_q[j][sl];
            S.x += a.x; S.y += a.y; S.z += a.z; S.w += a.w;
            Q.x += c.x; Q.y += c.y; Q.z += c.z; Q.w += c.w;
        }

        const float4 t   = sm_t[sl];
        const float4 usr = sm_u[sl];

        const float tsc = renorm_scale(half_sum(t.x * t.x + t.y * t.y +
                                                t.z * t.z + t.w * t.w));
        float4 items;
        items.x = S.x * S.x - Q.x + t.x * tsc;
        items.y = S.y * S.y - Q.y + t.y * tsc;
        items.z = S.z * S.z - Q.z + t.z * tsc;
        items.w = S.w * S.w - Q.w + t.w * tsc;

        const float usc = renorm_scale(half_sum(usr.x * usr.x + usr.y * usr.y +
                                                usr.z * usr.z + usr.w * usr.w));
        const float dot = half_sum((usr.x * items.x + usr.y * items.y +
                                    usr.z * items.z + usr.w * items.w) * usc);
        if (lane == 0) out[b] = 1.0f / (1.0f + expf(-dot));
    }
}

extern "C" void kernel_launch(void* const* d_in, const int* in_sizes, int n_in,
                              void* d_out, int out_size)
{
    const float* entity_emb = (const float*)d_in[0];
    const float* user_emb   = (const float*)d_in[1];
    // d_in[2..5] = Wa, ba, Wh, bh : dead code (softmax over singleton axis == 1)
    const int* u         = (const int*)d_in[6];
    const int* item_ids  = (const int*)d_in[7];
    const int* nbr1_idx  = (const int*)d_in[8];
    const int* node_ids0 = (const int*)d_in[9];
    const int* nbr0      = (const int*)d_in[10];

    const int B  = in_sizes[6];   // 2048
    const int n0 = in_sizes[9];   // 65536

    // hop 0: one warp per node, 4 warps per block
    {
        const int wpb = 4;
        const int blocks = (n0 + wpb - 1) / wpb;
        hop0_kernel<<<blocks, wpb * 32>>>(entity_emb, node_ids0, nbr0, n0);
    }
    // hop 1: one block (4 warps) per batch row
    hop1_kernel<<<B, 128>>>(entity_emb, user_emb, u, item_ids, nbr1_idx,
                            (float*)d_out, B);
}

// round 17
// speedup vs baseline: 1.2738x; 1.0242x over previous
#include <cuda_runtime.h>
#include <math.h>

#define KDIM 64
#define DEG 32
#define N0_MAX 65536

// hop-0 aggregate scratch: 65536 x 64 f32 = 16 MB (static __device__, no alloc)
__device__ float g_agg0[N0_MAX * KDIM];

// reduce across a 16-lane half-warp (xor 8,4,2,1)
__device__ __forceinline__ float half_sum(float v) {
#pragma unroll
    for (int o = 8; o > 0; o >>= 1) v += __shfl_xor_sync(0xffffffffu, v, o);
    return v;
}

// renorm scale: min(1, 1/max(sqrt(ss), 1e-12)) == ss > 1 ? rsqrt(ss) : 1
__device__ __forceinline__ float renorm_scale(float ss) {
    return (ss > 1.0f) ? rsqrtf(ss) : 1.0f;
}

// ============================ hop 0 ============================
// Champion (66us; LTS/DRAM roofline for random 256B gathers). One warp per
// node; half-warp sub covers neighbors {16*sub+i}; lane sl owns dims
// [4sl,4sl+3]; all 16 rows prefetched into registers (MLP 16). No loop state
// may be added here — it breaks ptxas's load batching (measured R5/R15).
__global__ void __launch_bounds__(128) hop0_kernel(
    const float* __restrict__ entity_emb,
    const int* __restrict__ node_ids0,
    const int* __restrict__ nbr0,
    int n0)
{
    const int node = blockIdx.x * (blockDim.x >> 5) + (threadIdx.x >> 5);
    const int lane = threadIdx.x & 31;
    const int sub  = lane >> 4;
    const int sl   = lane & 15;
    if (node >= n0) return;

    const int myidx = __ldg(nbr0 + (size_t)node * DEG + lane);
    const int tid   = __ldg(node_ids0 + node);

    float4 e[16];
#pragma unroll
    for (int i = 0; i < 16; i++) {
        const int id = __shfl_sync(0xffffffffu, myidx, i + (sub << 4));
        e[i] = __ldg((const float4*)(entity_emb + (size_t)id * KDIM) + sl);
    }
    float4 t = __ldg((const float4*)(entity_emb + (size_t)tid * KDIM) + sl);

    float4 s = make_float4(0.f, 0.f, 0.f, 0.f);
    float4 q = make_float4(0.f, 0.f, 0.f, 0.f);
#pragma unroll
    for (int i = 0; i < 16; i++) {
        const float ss = half_sum(e[i].x * e[i].x + e[i].y * e[i].y +
                                  e[i].z * e[i].z + e[i].w * e[i].w);
        const float sc = renorm_scale(ss);
        const float ex = e[i].x * sc, ey = e[i].y * sc;
        const float ez = e[i].z * sc, ew = e[i].w * sc;
        s.x += ex; s.y += ey; s.z += ez; s.w += ew;
        q.x += ex * ex; q.y += ey * ey; q.z += ez * ez; q.w += ew * ew;
    }

    s.x += __shfl_xor_sync(0xffffffffu, s.x, 16);
    s.y += __shfl_xor_sync(0xffffffffu, s.y, 16);
    s.z += __shfl_xor_sync(0xffffffffu, s.z, 16);
    s.w += __shfl_xor_sync(0xffffffffu, s.w, 16);
    q.x += __shfl_xor_sync(0xffffffffu, q.x, 16);
    q.y += __shfl_xor_sync(0xffffffffu, q.y, 16);
    q.z += __shfl_xor_sync(0xffffffffu, q.z, 16);
    q.w += __shfl_xor_sync(0xffffffffu, q.w, 16);

    const float tsc = renorm_scale(half_sum(t.x * t.x + t.y * t.y +
                                            t.z * t.z + t.w * t.w));

    if (sub == 0) {
        float4 o;
        o.x = s.x * s.x - q.x + t.x * tsc;
        o.y = s.y * s.y - q.y + t.y * tsc;
        o.z = s.z * s.z - q.z + t.z * tsc;
        o.w = s.w * s.w - q.w + t.w * tsc;
        *((float4*)(g_agg0 + (size_t)node * KDIM) + sl) = o;
    }
}

// ============================ hop 1 ============================
// Champion (~7.4us): one block (4 warps) per row; warps 1 & 2 prefetch
// item/user rows into smem at the top (overlapped with agg0 gathers); warp 0
// epilogue reads smem only; agg0 gathers via the read-only nc path.
__global__ void __launch_bounds__(128) hop1_kernel(
    const float* __restrict__ entity_emb,
    const float* __restrict__ user_emb,
    const int* __restrict__ u,
    const int* __restrict__ item_ids,
    const int* __restrict__ nbr1_idx,
    float* __restrict__ out,
    int B)
{
    __shared__ float4 sm_s[4][16];
    __shared__ float4 sm_q[4][16];
    __shared__ float4 sm_t[16];
    __shared__ float4 sm_u[16];

    const int b    = blockIdx.x;
    const int w    = threadIdx.x >> 5;
    const int lane = threadIdx.x & 31;
    const int sub  = lane >> 4;
    const int sl   = lane & 15;
    if (b >= B) return;

    // top-of-kernel prefetch: warp 1 loads item row, warp 2 loads user row
    if (w == 1 && sub == 0) {
        const int it = __ldg(item_ids + b);
        sm_t[sl] = __ldg((const float4*)(entity_emb + (size_t)it * KDIM) + sl);
    }
    if (w == 2 && sub == 0) {
        const int uid = __ldg(u + b);
        sm_u[sl] = __ldg((const float4*)(user_emb + (size_t)uid * KDIM) + sl);
    }

    // lanes 0-7 hold this warp's 8 neighbor indices
    const int myidx = (lane < 8)
        ? __ldg(nbr1_idx + (size_t)b * DEG + w * 8 + lane) : 0;

    float4 e[4];
#pragma unroll
    for (int i = 0; i < 4; i++) {
        const int id = __shfl_sync(0xffffffffu, myidx, (sub << 2) + i);
        e[i] = __ldg((const float4*)(g_agg0 + (size_t)id * KDIM) + sl);
    }

    float4 s = make_float4(0.f, 0.f, 0.f, 0.f);
    float4 q = make_float4(0.f, 0.f, 0.f, 0.f);
#pragma unroll
    for (int i = 0; i < 4; i++) {
        s.x += e[i].x; s.y += e[i].y; s.z += e[i].z; s.w += e[i].w;
        q.x += e[i].x * e[i].x; q.y += e[i].y * e[i].y;
        q.z += e[i].z * e[i].z; q.w += e[i].w * e[i].w;
    }

    s.x += __shfl_xor_sync(0xffffffffu, s.x, 16);
    s.y += __shfl_xor_sync(0xffffffffu, s.y, 16);
    s.z += __shfl_xor_sync(0xffffffffu, s.z, 16);
    s.w += __shfl_xor_sync(0xffffffffu, s.w, 16);
    q.x += __shfl_xor_sync(0xffffffffu, q.x, 16);
    q.y += __shfl_xor_sync(0xffffffffu, q.y, 16);
    q.z += __shfl_xor_sync(0xffffffffu, q.z, 16);
    q.w += __shfl_xor_sync(0xffffffffu, q.w, 16);

    if (sub == 0) { sm_s[w][sl] = s; sm_q[w][sl] = q; }
    __syncthreads();

    if (w == 0) {
        float4 S = sm_s[0][sl], Q = sm_q[0][sl];
#pragma unroll
        for (int j = 1; j < 4; j++) {
            const float4 a = sm_s[j][sl], c = sm_q[j][sl];
            S.x += a.x; S.y += a.y; S.z += a.z; S.w += a.w;
            Q.x += c.x; Q.y += c.y; Q.z += c.z; Q.w += c.w;
        }

        const float4 t   = sm_t[sl];
        const float4 usr = sm_u[sl];

        const float tsc = renorm_scale(half_sum(t.x * t.x + t.y * t.y +
                                                t.z * t.z + t.w * t.w));
        float4 items;
        items.x = S.x * S.x - Q.x + t.x * tsc;
        items.y = S.y * S.y - Q.y + t.y * tsc;
        items.z = S.z * S.z - Q.z + t.z * tsc;
        items.w = S.w * S.w - Q.w + t.w * tsc;

        const float usc = renorm_scale(half_sum(usr.x * usr.x + usr.y * usr.y +
                                                usr.z * usr.z + usr.w * usr.w));
        const float dot = half_sum((usr.x * items.x + usr.y * items.y +
                                    usr.z * items.z + usr.w * items.w) * usc);
        if (lane == 0) out[b] = 1.0f / (1.0f + expf(-dot));
    }
}

extern "C" void kernel_launch(void* const* d_in, const int* in_sizes, int n_in,
                              void* d_out, int out_size)
{
    const float* entity_emb = (const float*)d_in[0];
    const float* user_emb   = (const float*)d_in[1];
    // d_in[2..5] = Wa, ba, Wh, bh : dead code (softmax over singleton axis == 1)
    const int* u         = (const int*)d_in[6];
    const int* item_ids  = (const int*)d_in[7];
    const int* nbr1_idx  = (const int*)d_in[8];
    const int* node_ids0 = (const int*)d_in[9];
    const int* nbr0      = (const int*)d_in[10];

    const int B  = in_sizes[6];   // 2048
    const int n0 = in_sizes[9];   // 65536

    // hop 0: one warp per node, 4 warps per block
    {
        const int wpb = 4;
        const int blocks = (n0 + wpb - 1) / wpb;
        hop0_kernel<<<blocks, wpb * 32>>>(entity_emb, node_ids0, nbr0, n0);
    }
    // hop 1: one block (4 warps) per batch row
    hop1_kernel<<<B, 128>>>(entity_emb, user_emb, u, item_ids, nbr1_idx,
                            (float*)d_out, B);
}